// round 9
// baseline (speedup 1.0000x reference)
#include <cuda_runtime.h>
#include <cstdint>

#define BB 16
#define SS 2048
#define DD 512
#define ROWSTR 16                  // smem row stride in floats (no pad; x4-perm is conflict-free)
#define STAGE_F (128 * ROWSTR)     // floats per 16-k stage per operand (2048 = 8KB)
#define SUPER_F (2 * STAGE_F)      // floats per 32-k superstage (16KB)
#define NSUPER 3                   // superstage ring

// ---------------- device scratch ----------------
__device__ float g_a[BB * SS];
__device__ float g_c[BB * SS];
__device__ int   g_segstart[BB * (SS + 1)];
__device__ int   g_nwords[BB];
__device__ float g_mean[(size_t)BB * SS * DD];   // tf32-rounded, x4-k-permuted means
__device__ float g_wcT[DD * DD];                 // w_comb^T [N][K], tf32-rounded, permuted

__device__ __forceinline__ uint32_t f2tf32(float v) {
    uint32_t r;
    asm("cvt.rna.tf32.f32 %0, %1;" : "=r"(r) : "f"(v));
    return r;
}
__device__ __forceinline__ uint32_t smem_u32(const void* p) {
    uint32_t a;
    asm("{ .reg .u64 t; cvta.to.shared.u64 t, %1; cvt.u32.u64 %0, t; }" : "=r"(a) : "l"(p));
    return a;
}
#define CP16(dst, src) \
    asm volatile("cp.async.cg.shared.global [%0], [%1], 16;" :: "r"(dst), "l"(src))
#define CP_COMMIT() asm volatile("cp.async.commit_group;" ::: "memory")
#define CP_WAIT1()  asm volatile("cp.async.wait_group 1;" ::: "memory")

__device__ __forceinline__ void mma_tf32(float c[4], uint32_t a0, uint32_t a1,
                                         uint32_t a2, uint32_t a3,
                                         uint32_t b0, uint32_t b1) {
    asm volatile(
        "mma.sync.aligned.m16n8k8.row.col.f32.tf32.tf32.f32 "
        "{%0,%1,%2,%3}, {%4,%5,%6,%7}, {%8,%9}, {%0,%1,%2,%3};"
        : "+f"(c[0]), "+f"(c[1]), "+f"(c[2]), "+f"(c[3])
        : "r"(a0), "r"(a1), "r"(a2), "r"(a3), "r"(b0), "r"(b1));
}

// ---------------- K1: per-frame score dots ----------------
__global__ void k_scores(const float* __restrict__ frame, const float* __restrict__ wscore) {
    int warp = (blockIdx.x * blockDim.x + threadIdx.x) >> 5;
    int lane = threadIdx.x & 31;
    if (warp >= BB * SS) return;
    const float4* row = (const float4*)(frame + (size_t)warp * DD);
    const float4* w1  = (const float4*)wscore;
    const float4* w2  = (const float4*)(wscore + DD);
    float d1 = 0.f, d2 = 0.f;
#pragma unroll
    for (int k = 0; k < 4; k++) {
        int i = lane + k * 32;
        float4 f = row[i];
        float4 a = w1[i];
        float4 b = w2[i];
        d1 += f.x * a.x + f.y * a.y + f.z * a.z + f.w * a.w;
        d2 += f.x * b.x + f.y * b.y + f.z * b.z + f.w * b.w;
    }
#pragma unroll
    for (int off = 16; off; off >>= 1) {
        d1 += __shfl_down_sync(0xFFFFFFFFu, d1, off);
        d2 += __shfl_down_sync(0xFFFFFFFFu, d2, off);
    }
    if (lane == 0) { g_a[warp] = d1; g_c[warp] = d2; }
}

// ---------------- K2: per-batch segment scan ----------------
__global__ void k_scan(const float* __restrict__ bscore_p, float* __restrict__ out_tail) {
    int b   = blockIdx.x;
    int tid = threadIdx.x;
    float bs = *bscore_p;
    int t0 = tid * 2, t1 = t0 + 1;
    int s0 = (t0 == 0) ? 0
             : (((g_a[b * SS + t0 - 1] + g_c[b * SS + t0] + bs) > 0.5f) ? 0 : 1);
    int s1 = (((g_a[b * SS + t1 - 1] + g_c[b * SS + t1] + bs) > 0.5f) ? 0 : 1);

    __shared__ int sc[1024];
    sc[tid] = s0 + s1;
    __syncthreads();
    for (int off = 1; off < 1024; off <<= 1) {
        int v   = sc[tid];
        int add = (tid >= off) ? sc[tid - off] : 0;
        __syncthreads();
        sc[tid] = v + add;
        __syncthreads();
    }
    int excl = (tid == 0) ? 0 : sc[tid - 1];
    int seg0 = excl + s0;
    int seg1 = excl + s0 + s1;

    int base = b * (SS + 1);
    if (t0 == 0 || s0 == 1) g_segstart[base + seg0] = t0;
    if (s1 == 1)            g_segstart[base + seg1] = t1;
    if (t1 == SS - 1) {
        int nw = seg1 + 1;
        g_nwords[b] = nw;
        g_segstart[base + nw] = SS;
        if (out_tail) out_tail[b] = (float)nw;
    }
}

// ---------------- K3: segment means (tf32, x4-k-permuted) ----------------
// warp per word; lane owns 16 consecutive k. Permuted store:
// pos 4q+m (within 16-group) holds orig k = q + 4m  ->  uint4 at 4q = {q, q+4, q+8, q+12}.
__global__ void k_mean(const float* __restrict__ frame) {
    int j = blockIdx.x * 4 + (threadIdx.x >> 5);   // word index
    int lane = threadIdx.x & 31;
    int b = j / SS, w = j % SS;
    if (w >= g_nwords[b]) return;
    int base = b * (SS + 1);
    int st = g_segstart[base + w];
    int en = g_segstart[base + w + 1];
    float inv = 1.0f / (float)(en - st);
    float a[16];
#pragma unroll
    for (int i = 0; i < 16; i++) a[i] = 0.f;
    for (int t = st; t < en; t++) {
        const float4* p = (const float4*)(frame + ((size_t)(b * SS + t)) * DD + lane * 16);
#pragma unroll
        for (int q = 0; q < 4; q++) {
            float4 v = p[q];
            a[q * 4 + 0] += v.x; a[q * 4 + 1] += v.y;
            a[q * 4 + 2] += v.z; a[q * 4 + 3] += v.w;
        }
    }
    uint4* dst = (uint4*)(g_mean + (size_t)j * DD + lane * 16);
#pragma unroll
    for (int q = 0; q < 4; q++) {
        uint4 o;
        o.x = f2tf32(a[q] * inv);
        o.y = f2tf32(a[q + 4] * inv);
        o.z = f2tf32(a[q + 8] * inv);
        o.w = f2tf32(a[q + 12] * inv);
        dst[q] = o;
    }
}

// ---------------- K3b: w_comb -> g_wcT[N][K] transposed, rounded, x4-permuted ------
__global__ void k_wcT(const float* __restrict__ wc) {
    __shared__ float t[32][33];
    int k0 = blockIdx.y * 32, n0 = blockIdx.x * 32;
    int x = threadIdx.x, y0 = threadIdx.y;     // 32 x 8
#pragma unroll
    for (int dy = 0; dy < 32; dy += 8)
        t[y0 + dy][x] = wc[(size_t)(k0 + y0 + dy) * DD + n0 + x];
    __syncthreads();
#pragma unroll
    for (int dy = 0; dy < 32; dy += 8) {
        int k = k0 + x;
        int kp = (k & ~15) | (4 * (k & 3)) | ((k >> 2) & 3);
        g_wcT[(size_t)(n0 + y0 + dy) * DD + kp] =
            __uint_as_float(f2tf32(t[x][y0 + dy]));
    }
}

// ---------------- K4: tf32 mma.sync GEMM, 3-superstage cp.async, LDS.128 frags -----
// 256 thr, 8 warps 4x2, warp tile 32x64. Superstage = 32 k (2 ktiles) per barrier.
__global__ void __launch_bounds__(256, 2)
k_gemm_tc(const float* __restrict__ bc, float* __restrict__ out) {
    int b    = blockIdx.z;
    int row0 = blockIdx.y * 128;
    int col0 = blockIdx.x * 128;
    int nw   = g_nwords[b];
    int tid  = threadIdx.x;
    float* outbase = out + (size_t)b * SS * DD;

    if (row0 >= nw) {
        float4 z = make_float4(0.f, 0.f, 0.f, 0.f);
        for (int i = tid; i < 128 * 32; i += 256) {
            int r = i >> 5, cq = i & 31;
            ((float4*)(outbase + (size_t)(row0 + r) * DD + col0))[cq] = z;
        }
        return;
    }

    extern __shared__ float sm[];
    float* AsB = sm;                          // NSUPER * SUPER_F
    float* BsB = sm + NSUPER * SUPER_F;

    const float* A  = g_mean + ((size_t)b * SS + row0) * DD;
    const float* Bm = g_wcT + (size_t)col0 * DD;

    uint32_t aA = smem_u32(AsB), aB = smem_u32(BsB);
    // per-thread cp.async mapping: row = tid>>1, stage-in-super = tid&1, 4 chunks of 16B
    int   rS = tid >> 1, nS = tid & 1;
    uint32_t dOf = (uint32_t)nS * (STAGE_F * 4) + (uint32_t)rS * 64;

    int wid  = tid >> 5;
    int lane = tid & 31;
    int wm   = wid & 3;                       // warp row (x32)
    int wn   = wid >> 2;                      // warp col (x64)
    int gid  = lane >> 2;
    int tq   = lane & 3;

    float acc[2][8][4];
#pragma unroll
    for (int mt = 0; mt < 2; mt++)
#pragma unroll
        for (int nt = 0; nt < 8; nt++)
#pragma unroll
            for (int i = 0; i < 4; i++) acc[mt][nt][i] = 0.f;

    // prologue: superstages 0,1
#pragma unroll
    for (int p = 0; p < 2; p++) {
        uint32_t sb = p * (SUPER_F * 4);
        const float* ga = A + (size_t)rS * DD + p * 32 + nS * 16;
        const float* gb = Bm + (size_t)rS * DD + p * 32 + nS * 16;
#pragma unroll
        for (int q = 0; q < 4; q++) {
            CP16(aA + sb + dOf + q * 16, ga + q * 4);
            CP16(aB + sb + dOf + q * 16, gb + q * 4);
        }
        CP_COMMIT();
    }

    const int NIT = DD / 32;                  // 16 superstages
    for (int it = 0; it < NIT; it++) {
        CP_WAIT1();
        __syncthreads();

        if (it + 2 < NIT) {
            int p = it + 2;
            uint32_t sb = (uint32_t)(p % 3) * (SUPER_F * 4);
            const float* ga = A + (size_t)rS * DD + p * 32 + nS * 16;
            const float* gb = Bm + (size_t)rS * DD + p * 32 + nS * 16;
#pragma unroll
            for (int q = 0; q < 4; q++) {
                CP16(aA + sb + dOf + q * 16, ga + q * 4);
                CP16(aB + sb + dOf + q * 16, gb + q * 4);
            }
        }
        CP_COMMIT();

        // compute 2 ktiles of this superstage
#pragma unroll
        for (int n = 0; n < 2; n++) {
            const float* as = AsB + (it % 3) * SUPER_F + n * STAGE_F;
            const float* bs = BsB + (it % 3) * SUPER_F + n * STAGE_F;

            // A fragments: 4 x LDS.128 (both ks halves)
            float4 pa[2][2];
#pragma unroll
            for (int mt = 0; mt < 2; mt++) {
                int rb = wm * 32 + mt * 16 + gid;
                pa[mt][0] = *(const float4*)(as + rb * ROWSTR + 4 * tq);
                pa[mt][1] = *(const float4*)(as + (rb + 8) * ROWSTR + 4 * tq);
            }
            // B fragments in two groups of 4 nt (caps live registers)
#pragma unroll
            for (int bg = 0; bg < 2; bg++) {
                float4 pb[4];
#pragma unroll
                for (int j = 0; j < 4; j++) {
                    int nb = wn * 64 + (bg * 4 + j) * 8 + gid;
                    pb[j] = *(const float4*)(bs + nb * ROWSTR + 4 * tq);
                }
#pragma unroll
                for (int mt = 0; mt < 2; mt++)
#pragma unroll
                    for (int j = 0; j < 4; j++) {
                        int nt = bg * 4 + j;
                        // ks0: orig k = tq, tq+4  (v.x, v.y)
                        mma_tf32(acc[mt][nt],
                                 __float_as_uint(pa[mt][0].x), __float_as_uint(pa[mt][1].x),
                                 __float_as_uint(pa[mt][0].y), __float_as_uint(pa[mt][1].y),
                                 __float_as_uint(pb[j].x), __float_as_uint(pb[j].y));
                        // ks1: orig k = tq+8, tq+12 (v.z, v.w)
                        mma_tf32(acc[mt][nt],
                                 __float_as_uint(pa[mt][0].z), __float_as_uint(pa[mt][1].z),
                                 __float_as_uint(pa[mt][0].w), __float_as_uint(pa[mt][1].w),
                                 __float_as_uint(pb[j].z), __float_as_uint(pb[j].w));
                    }
            }
        }
    }

    // epilogue: bias + zero padded rows, direct stores
#pragma unroll
    for (int mt = 0; mt < 2; mt++) {
        int r0g = row0 + wm * 32 + mt * 16 + gid;
        int r1g = r0g + 8;
#pragma unroll
        for (int nt = 0; nt < 8; nt++) {
            int col = col0 + wn * 64 + nt * 8 + 2 * tq;
            float2 bias = *(const float2*)(bc + col);
            float2 v0, v1;
            if (r0g < nw) {
                v0.x = acc[mt][nt][0] + bias.x;
                v0.y = acc[mt][nt][1] + bias.y;
            } else { v0.x = 0.f; v0.y = 0.f; }
            if (r1g < nw) {
                v1.x = acc[mt][nt][2] + bias.x;
                v1.y = acc[mt][nt][3] + bias.y;
            } else { v1.x = 0.f; v1.y = 0.f; }
            *(float2*)(outbase + (size_t)r0g * DD + col) = v0;
            *(float2*)(outbase + (size_t)r1g * DD + col) = v1;
        }
    }
}

// ---------------- launcher ----------------
extern "C" void kernel_launch(void* const* d_in, const int* in_sizes, int n_in,
                              void* d_out, int out_size) {
    const float* frame  = (const float*)d_in[0];   // [B,S,D]
    const float* wscore = (const float*)d_in[1];   // [2D,1]
    const float* bscore = (const float*)d_in[2];   // [1]
    const float* wcomb  = (const float*)d_in[3];   // [D,D]
    const float* bcomb  = (const float*)d_in[4];   // [D]
    float* out = (float*)d_out;

    float* tail = (out_size >= BB * SS * DD + BB) ? out + (size_t)BB * SS * DD : nullptr;

    const int SMEM_DYN = 2 * NSUPER * SUPER_F * 4;    // 96 KB
    cudaFuncSetAttribute(k_gemm_tc, cudaFuncAttributeMaxDynamicSharedMemorySize, SMEM_DYN);

    k_wcT<<<dim3(DD / 32, DD / 32), dim3(32, 8)>>>(wcomb);
    k_scores<<<(BB * SS) / 8, 256>>>(frame, wscore);
    k_scan<<<BB, 1024>>>(bscore, tail);
    k_mean<<<(BB * SS) / 4, 128>>>(frame);
    dim3 grid(DD / 128, SS / 128, BB);
    k_gemm_tc<<<grid, 256, SMEM_DYN>>>(bcomb, out);
}

// round 10
// speedup vs baseline: 1.3916x; 1.3916x over previous
#include <cuda_runtime.h>
#include <cstdint>

#define BB 16
#define SS 2048
#define DD 512
#define NST 4                      // cp.async pipeline stages
#define ROWSTR 16                  // smem row stride in floats (x4-perm -> conflict-free LDS.128)
#define STAGE_F (128 * ROWSTR)     // floats per 16-k stage per operand (2048 = 8KB)

// ---------------- device scratch ----------------
__device__ float g_a[BB * SS];
__device__ float g_c[BB * SS];
__device__ int   g_segstart[BB * (SS + 1)];
__device__ int   g_nwords[BB];
__device__ float g_mean[(size_t)BB * SS * DD];   // tf32-rounded, x4-k-permuted means
__device__ float g_wcT[DD * DD];                 // w_comb^T [N][K], tf32-rounded, permuted

__device__ __forceinline__ uint32_t f2tf32(float v) {
    uint32_t r;
    asm("cvt.rna.tf32.f32 %0, %1;" : "=r"(r) : "f"(v));
    return r;
}
__device__ __forceinline__ uint32_t smem_u32(const void* p) {
    uint32_t a;
    asm("{ .reg .u64 t; cvta.to.shared.u64 t, %1; cvt.u32.u64 %0, t; }" : "=r"(a) : "l"(p));
    return a;
}
#define CP16(dst, src) \
    asm volatile("cp.async.cg.shared.global [%0], [%1], 16;" :: "r"(dst), "l"(src))
#define CP_COMMIT() asm volatile("cp.async.commit_group;" ::: "memory")
#define CP_WAIT2()  asm volatile("cp.async.wait_group 2;" ::: "memory")

__device__ __forceinline__ void mma_tf32(float c[4], uint32_t a0, uint32_t a1,
                                         uint32_t a2, uint32_t a3,
                                         uint32_t b0, uint32_t b1) {
    asm volatile(
        "mma.sync.aligned.m16n8k8.row.col.f32.tf32.tf32.f32 "
        "{%0,%1,%2,%3}, {%4,%5,%6,%7}, {%8,%9}, {%0,%1,%2,%3};"
        : "+f"(c[0]), "+f"(c[1]), "+f"(c[2]), "+f"(c[3])
        : "r"(a0), "r"(a1), "r"(a2), "r"(a3), "r"(b0), "r"(b1));
}

// ---------------- K1: per-frame score dots ----------------
__global__ void k_scores(const float* __restrict__ frame, const float* __restrict__ wscore) {
    int warp = (blockIdx.x * blockDim.x + threadIdx.x) >> 5;
    int lane = threadIdx.x & 31;
    if (warp >= BB * SS) return;
    const float4* row = (const float4*)(frame + (size_t)warp * DD);
    const float4* w1  = (const float4*)wscore;
    const float4* w2  = (const float4*)(wscore + DD);
    float d1 = 0.f, d2 = 0.f;
#pragma unroll
    for (int k = 0; k < 4; k++) {
        int i = lane + k * 32;
        float4 f = row[i];
        float4 a = w1[i];
        float4 b = w2[i];
        d1 += f.x * a.x + f.y * a.y + f.z * a.z + f.w * a.w;
        d2 += f.x * b.x + f.y * b.y + f.z * b.z + f.w * b.w;
    }
#pragma unroll
    for (int off = 16; off; off >>= 1) {
        d1 += __shfl_down_sync(0xFFFFFFFFu, d1, off);
        d2 += __shfl_down_sync(0xFFFFFFFFu, d2, off);
    }
    if (lane == 0) { g_a[warp] = d1; g_c[warp] = d2; }
}

// ---------------- K2: per-batch segment scan ----------------
__global__ void k_scan(const float* __restrict__ bscore_p, float* __restrict__ out_tail) {
    int b   = blockIdx.x;
    int tid = threadIdx.x;
    float bs = *bscore_p;
    int t0 = tid * 2, t1 = t0 + 1;
    int s0 = (t0 == 0) ? 0
             : (((g_a[b * SS + t0 - 1] + g_c[b * SS + t0] + bs) > 0.5f) ? 0 : 1);
    int s1 = (((g_a[b * SS + t1 - 1] + g_c[b * SS + t1] + bs) > 0.5f) ? 0 : 1);

    __shared__ int sc[1024];
    sc[tid] = s0 + s1;
    __syncthreads();
    for (int off = 1; off < 1024; off <<= 1) {
        int v   = sc[tid];
        int add = (tid >= off) ? sc[tid - off] : 0;
        __syncthreads();
        sc[tid] = v + add;
        __syncthreads();
    }
    int excl = (tid == 0) ? 0 : sc[tid - 1];
    int seg0 = excl + s0;
    int seg1 = excl + s0 + s1;

    int base = b * (SS + 1);
    if (t0 == 0 || s0 == 1) g_segstart[base + seg0] = t0;
    if (s1 == 1)            g_segstart[base + seg1] = t1;
    if (t1 == SS - 1) {
        int nw = seg1 + 1;
        g_nwords[b] = nw;
        g_segstart[base + nw] = SS;
        if (out_tail) out_tail[b] = (float)nw;
    }
}

// ---------------- K3: segment means (tf32, x4-k-permuted) ----------------
// 64 thr = 2 warps, one word per warp. Lane owns orig k 16L..16L+15.
// Store perm within 16-group: pos 4q+m holds orig k = 4m+q  ->  uint4 at 4q = {q,q+4,q+8,q+12}.
__global__ void k_mean(const float* __restrict__ frame) {
    int j = blockIdx.x * 2 + (threadIdx.x >> 5);   // word index
    int lane = threadIdx.x & 31;
    int b = j / SS, w = j % SS;
    if (w >= g_nwords[b]) return;
    int base = b * (SS + 1);
    int st = g_segstart[base + w];
    int en = g_segstart[base + w + 1];
    float inv = 1.0f / (float)(en - st);
    float a[16];
#pragma unroll
    for (int i = 0; i < 16; i++) a[i] = 0.f;
    for (int t = st; t < en; t++) {
        const float4* p = (const float4*)(frame + ((size_t)(b * SS + t)) * DD + lane * 16);
#pragma unroll
        for (int q = 0; q < 4; q++) {
            float4 v = p[q];
            a[q * 4 + 0] += v.x; a[q * 4 + 1] += v.y;
            a[q * 4 + 2] += v.z; a[q * 4 + 3] += v.w;
        }
    }
    uint4* dst = (uint4*)(g_mean + (size_t)j * DD + lane * 16);
#pragma unroll
    for (int q = 0; q < 4; q++) {
        uint4 o;
        o.x = f2tf32(a[q] * inv);
        o.y = f2tf32(a[q + 4] * inv);
        o.z = f2tf32(a[q + 8] * inv);
        o.w = f2tf32(a[q + 12] * inv);
        dst[q] = o;
    }
}

// ---------------- K3b: w_comb -> g_wcT[N][K] transposed, rounded, x4-permuted ------
__global__ void k_wcT(const float* __restrict__ wc) {
    __shared__ float t[32][33];
    int k0 = blockIdx.y * 32, n0 = blockIdx.x * 32;
    int x = threadIdx.x, y0 = threadIdx.y;     // 32 x 8
#pragma unroll
    for (int dy = 0; dy < 32; dy += 8)
        t[y0 + dy][x] = wc[(size_t)(k0 + y0 + dy) * DD + n0 + x];
    __syncthreads();
#pragma unroll
    for (int dy = 0; dy < 32; dy += 8) {
        int k = k0 + x;
        int kp = (k & ~15) | (4 * (k & 3)) | ((k >> 2) & 3);
        g_wcT[(size_t)(n0 + y0 + dy) * DD + kp] =
            __uint_as_float(f2tf32(t[x][y0 + dy]));
    }
}

// ---------------- K4: tf32 mma.sync GEMM (R7 skeleton + LDS.128 frags) ------------
// 256 thr, 8 warps 4x2, warp tile 32x64, 4-stage cp.async, 1 ktile (16 k) per barrier.
__global__ void __launch_bounds__(256, 2)
k_gemm_tc(const float* __restrict__ bc, float* __restrict__ out) {
    int b    = blockIdx.z;
    int row0 = blockIdx.y * 128;
    int col0 = blockIdx.x * 128;
    int nw   = g_nwords[b];
    int tid  = threadIdx.x;
    float* outbase = out + (size_t)b * SS * DD;

    if (row0 >= nw) {
        float4 z = make_float4(0.f, 0.f, 0.f, 0.f);
        for (int i = tid; i < 128 * 32; i += 256) {
            int r = i >> 5, cq = i & 31;
            ((float4*)(outbase + (size_t)(row0 + r) * DD + col0))[cq] = z;
        }
        return;
    }

    extern __shared__ float sm[];
    float* AsB = sm;                          // NST * STAGE_F
    float* BsB = sm + NST * STAGE_F;

    const float* A  = g_mean + ((size_t)b * SS + row0) * DD;
    const float* Bm = g_wcT + (size_t)col0 * DD;

    uint32_t aA = smem_u32(AsB), aB = smem_u32(BsB);
    // per-stage: 128 rows x 64B = 512 chunks/operand; 2 chunks per thread
    int r0c = tid >> 2, c0c = tid & 3;
    int r1c = (tid + 256) >> 2, c1c = (tid + 256) & 3;
    uint32_t d0 = (uint32_t)r0c * 64 + (uint32_t)c0c * 16;
    uint32_t d1 = (uint32_t)r1c * 64 + (uint32_t)c1c * 16;

    int wid  = tid >> 5;
    int lane = tid & 31;
    int wm   = wid & 3;                       // warp row (x32)
    int wn   = wid >> 2;                      // warp col (x64)
    int gid  = lane >> 2;
    int tq   = lane & 3;

    float acc[2][8][4];
#pragma unroll
    for (int mt = 0; mt < 2; mt++)
#pragma unroll
        for (int nt = 0; nt < 8; nt++)
#pragma unroll
            for (int i = 0; i < 4; i++) acc[mt][nt][i] = 0.f;

    // prologue: stages 0..2
#pragma unroll
    for (int p = 0; p < 3; p++) {
        uint32_t sb = p * (STAGE_F * 4);
        CP16(aA + sb + d0, A + (size_t)r0c * DD + p * 16 + c0c * 4);
        CP16(aA + sb + d1, A + (size_t)r1c * DD + p * 16 + c1c * 4);
        CP16(aB + sb + d0, Bm + (size_t)r0c * DD + p * 16 + c0c * 4);
        CP16(aB + sb + d1, Bm + (size_t)r1c * DD + p * 16 + c1c * 4);
        CP_COMMIT();
    }

    const int NKT = DD / 16;                  // 32
    for (int kt = 0; kt < NKT; kt++) {
        CP_WAIT2();
        __syncthreads();

        if (kt + 3 < NKT) {
            int p = kt + 3;
            uint32_t sb = (uint32_t)(p & 3) * (STAGE_F * 4);
            CP16(aA + sb + d0, A + (size_t)r0c * DD + p * 16 + c0c * 4);
            CP16(aA + sb + d1, A + (size_t)r1c * DD + p * 16 + c1c * 4);
            CP16(aB + sb + d0, Bm + (size_t)r0c * DD + p * 16 + c0c * 4);
            CP16(aB + sb + d1, Bm + (size_t)r1c * DD + p * 16 + c1c * 4);
        }
        CP_COMMIT();

        const float* as = AsB + (kt & 3) * STAGE_F;
        const float* bs = BsB + (kt & 3) * STAGE_F;

        // A fragments: 4 x LDS.128 covers both ks halves of the ktile
        float4 pa[2][2];
#pragma unroll
        for (int mt = 0; mt < 2; mt++) {
            int rb = wm * 32 + mt * 16 + gid;
            pa[mt][0] = *(const float4*)(as + rb * ROWSTR + 4 * tq);
            pa[mt][1] = *(const float4*)(as + (rb + 8) * ROWSTR + 4 * tq);
        }
        // B fragments in 2 groups of 4 nt, interleaved with MMAs (caps live regs)
#pragma unroll
        for (int bg = 0; bg < 2; bg++) {
            float4 pb[4];
#pragma unroll
            for (int jj = 0; jj < 4; jj++) {
                int nb = wn * 64 + (bg * 4 + jj) * 8 + gid;
                pb[jj] = *(const float4*)(bs + nb * ROWSTR + 4 * tq);
            }
#pragma unroll
            for (int mt = 0; mt < 2; mt++)
#pragma unroll
                for (int jj = 0; jj < 4; jj++) {
                    int nt = bg * 4 + jj;
                    // ks0: orig k = tq, tq+4 (.x, .y)
                    mma_tf32(acc[mt][nt],
                             __float_as_uint(pa[mt][0].x), __float_as_uint(pa[mt][1].x),
                             __float_as_uint(pa[mt][0].y), __float_as_uint(pa[mt][1].y),
                             __float_as_uint(pb[jj].x), __float_as_uint(pb[jj].y));
                    // ks1: orig k = tq+8, tq+12 (.z, .w)
                    mma_tf32(acc[mt][nt],
                             __float_as_uint(pa[mt][0].z), __float_as_uint(pa[mt][1].z),
                             __float_as_uint(pa[mt][0].w), __float_as_uint(pa[mt][1].w),
                             __float_as_uint(pb[jj].z), __float_as_uint(pb[jj].w));
                }
        }
    }

    // epilogue: bias + zero padded rows, direct stores
#pragma unroll
    for (int mt = 0; mt < 2; mt++) {
        int r0g = row0 + wm * 32 + mt * 16 + gid;
        int r1g = r0g + 8;
#pragma unroll
        for (int nt = 0; nt < 8; nt++) {
            int col = col0 + wn * 64 + nt * 8 + 2 * tq;
            float2 bias = *(const float2*)(bc + col);
            float2 v0, v1;
            if (r0g < nw) {
                v0.x = acc[mt][nt][0] + bias.x;
                v0.y = acc[mt][nt][1] + bias.y;
            } else { v0.x = 0.f; v0.y = 0.f; }
            if (r1g < nw) {
                v1.x = acc[mt][nt][2] + bias.x;
                v1.y = acc[mt][nt][3] + bias.y;
            } else { v1.x = 0.f; v1.y = 0.f; }
            *(float2*)(outbase + (size_t)r0g * DD + col) = v0;
            *(float2*)(outbase + (size_t)r1g * DD + col) = v1;
        }
    }
}

// ---------------- launcher ----------------
extern "C" void kernel_launch(void* const* d_in, const int* in_sizes, int n_in,
                              void* d_out, int out_size) {
    const float* frame  = (const float*)d_in[0];   // [B,S,D]
    const float* wscore = (const float*)d_in[1];   // [2D,1]
    const float* bscore = (const float*)d_in[2];   // [1]
    const float* wcomb  = (const float*)d_in[3];   // [D,D]
    const float* bcomb  = (const float*)d_in[4];   // [D]
    float* out = (float*)d_out;

    float* tail = (out_size >= BB * SS * DD + BB) ? out + (size_t)BB * SS * DD : nullptr;

    const int SMEM_DYN = 2 * NST * STAGE_F * 4;    // 64 KB
    cudaFuncSetAttribute(k_gemm_tc, cudaFuncAttributeMaxDynamicSharedMemorySize, SMEM_DYN);

    k_wcT<<<dim3(DD / 32, DD / 32), dim3(32, 8)>>>(wcomb);
    k_scores<<<(BB * SS) / 8, 256>>>(frame, wscore);
    k_scan<<<BB, 1024>>>(bscore, tail);
    k_mean<<<(BB * SS) / 2, 64>>>(frame);
    dim3 grid(DD / 128, SS / 128, BB);
    k_gemm_tc<<<grid, 256, SMEM_DYN>>>(bcomb, out);
}